// round 15
// baseline (speedup 1.0000x reference)
#include <cuda_runtime.h>

#define NC   21
#define NC2  (NC * NC)
#define NB   8
#define HW   (512 * 512)
#define Q    (HW / 4)            // float4 groups per channel plane (65536)
#define TPB  1024
#define NBLOCKS 148              // 1 CTA per SM, all resident: zero tail
#define NWT  16384               // total warp-tiles (32 groups = 512 B each)
#define WT_BASE (NWT / NBLOCKS)  // 110
#define WT_REM  (NWT % NBLOCKS)  // 104 blocks get one extra warp-tile

// Scratch: per-sample confusion matrices conf[b][true][pred].
__device__ int g_conf[NB * NC2];
__device__ unsigned int g_done;   // zero-init; reset by last block each run

__device__ __forceinline__ float4 ldcs256(const float4* p) {
    float4 v;
    asm volatile("ld.global.cs.L2::256B.v4.f32 {%0,%1,%2,%3}, [%4];"
                 : "=f"(v.x), "=f"(v.y), "=f"(v.z), "=f"(v.w)
                 : "l"(p));
    return v;
}

// Order-preserving float->uint transform (total order, -inf..+inf ascending).
__device__ __forceinline__ unsigned monou(float f) {
    unsigned u = __float_as_uint(f);
    return u ^ ((unsigned)((int)u >> 31) | 0x80000000u);
}
// Pack (value, channel) so unsigned max == argmax with first-index tie-break.
// Low 5 bits hold (31-c): ties on the top-27 value bits keep the earlier c.
__device__ __forceinline__ unsigned pk(float f, unsigned c) {
    return (monou(f) & 0xFFFFFFE0u) | (31u - c);
}
#define UPD4(st, vv, c) \
    st[0] = max(st[0], pk((vv).x, (c))); \
    st[1] = max(st[1], pk((vv).y, (c))); \
    st[2] = max(st[2], pk((vv).z, (c))); \
    st[3] = max(st[3], pk((vv).w, (c)));

__global__ void __launch_bounds__(TPB, 1)
conf_kernel(const float* __restrict__ pred,
            const float* __restrict__ tgt,
            float* __restrict__ out) {
    __shared__ int sconf[2][NC2];   // two banks: chunk may straddle 1 sample boundary
    for (int i = threadIdx.x; i < 2 * NC2; i += TPB) (&sconf[0][0])[i] = 0;
    __syncthreads();

    const int j = blockIdx.x;
    const int wt = WT_BASE + (j < WT_REM ? 1 : 0);
    const int start = 32 * (j * WT_BASE + (j < WT_REM ? j : WT_REM));
    const int end = start + wt * 32;    // contiguous group range [start, end)

    for (int base = start; base < end; base += 2 * TPB) {
        const int g0 = base + threadIdx.x;
        const int g1 = g0 + TPB;
        const bool h0 = g0 < end;
        const bool h1 = g1 < end;

        const int b0 = g0 >> 16, p0 = g0 & (Q - 1);
        const int b1 = g1 >> 16, p1 = g1 & (Q - 1);

        const float4* P0 = reinterpret_cast<const float4*>(pred) + (size_t)b0 * NC * Q + p0;
        const float4* T0 = reinterpret_cast<const float4*>(tgt)  + (size_t)b0 * NC * Q + p0;
        const float4* P1 = reinterpret_cast<const float4*>(pred) + (size_t)b1 * NC * Q + p1;
        const float4* T1 = reinterpret_cast<const float4*>(tgt)  + (size_t)b1 * NC * Q + p1;

        unsigned sP0[4], sT0[4], sP1[4], sT1[4];
        #pragma unroll
        for (int k = 0; k < 4; k++) { sP0[k] = sT0[k] = sP1[k] = sT1[k] = 0; }

        if (h0) {
            #pragma unroll
            for (int c = 0; c < NC; c++) {
                float4 v = ldcs256(P0 + (size_t)c * Q);
                float4 w = ldcs256(T0 + (size_t)c * Q);
                UPD4(sP0, v, c); UPD4(sT0, w, c);
                if (h1) {
                    float4 v1 = ldcs256(P1 + (size_t)c * Q);
                    float4 w1 = ldcs256(T1 + (size_t)c * Q);
                    UPD4(sP1, v1, c); UPD4(sT1, w1, c);
                }
            }
        }

        if (h0) {
            int* sc = sconf[b0 & 1];
            #pragma unroll
            for (int k = 0; k < 4; k++) {
                unsigned pc = 31u - (sP0[k] & 31u);
                unsigned tc = 31u - (sT0[k] & 31u);
                atomicAdd(&sc[tc * NC + pc], 1);
            }
        }
        if (h1) {
            int* sc = sconf[b1 & 1];
            #pragma unroll
            for (int k = 0; k < 4; k++) {
                unsigned pc = 31u - (sP1[k] & 31u);
                unsigned tc = 31u - (sT1[k] & 31u);
                atomicAdd(&sc[tc * NC + pc], 1);
            }
        }
    }

    __syncthreads();

    // Flush: map banks back to the (at most two) samples this block touched.
    const int b_lo = start >> 16;
    const int b_hi = (end - 1) >> 16;
    for (int i = threadIdx.x; i < NC2; i += TPB) {
        int v = sconf[b_lo & 1][i];
        if (v) atomicAdd(&g_conf[b_lo * NC2 + i], v);
        if (b_hi != b_lo) {
            int v2 = sconf[b_hi & 1][i];
            if (v2) atomicAdd(&g_conf[b_hi * NC2 + i], v2);
        }
    }

    // ---- last-block finalize ----
    __threadfence();
    __shared__ unsigned int s_rank;
    if (threadIdx.x == 0) s_rank = atomicAdd(&g_done, 1u);
    __syncthreads();
    if (s_rank != NBLOCKS - 1) return;

    __shared__ float iou_sum[NB];
    __shared__ int   valid_cnt[NB];
    int t = threadIdx.x;
    if (t < NB) { iou_sum[t] = 0.0f; valid_cnt[t] = 0; }
    if (t == 0) g_done = 0;                 // reset for next invocation
    __syncthreads();

    if (t < NB * NC) {
        int bb = t / NC;
        int c  = t - bb * NC;
        const int* cb = &g_conf[bb * NC2];
        int tpv = __ldcg(&cb[c * NC + c]);
        int row = 0, col = 0;
        #pragma unroll
        for (int k = 0; k < NC; k++) {
            row += __ldcg(&cb[c * NC + k]);   // TP + FN
            col += __ldcg(&cb[k * NC + c]);   // TP + FP
        }
        if (tpv > 0) {
            float iou = (float)tpv / (float)(row + col - tpv);
            atomicAdd(&iou_sum[bb], iou);
            atomicAdd(&valid_cnt[bb], 1);
        }
    }
    __syncthreads();

    // Re-zero scratch for the next invocation (all reads done above).
    for (int i = t; i < NB * NC2; i += TPB) g_conf[i] = 0;

    if (t == 0) {
        float s = 0.0f;
        #pragma unroll
        for (int bb = 0; bb < NB; bb++)
            s += iou_sum[bb] / fmaxf((float)valid_cnt[bb], 1.0f);
        out[0] = s / (float)NB;
    }
}

extern "C" void kernel_launch(void* const* d_in, const int* in_sizes, int n_in,
                              void* d_out, int out_size) {
    const float* pred = (const float*)d_in[0];
    const float* tgt  = (const float*)d_in[1];
    float* out = (float*)d_out;

    conf_kernel<<<NBLOCKS, TPB>>>(pred, tgt, out);
}

// round 16
// speedup vs baseline: 1.0904x; 1.0904x over previous
#include <cuda_runtime.h>
#include <cstdint>

#define NC   21
#define NC2  (NC * NC)
#define NB   8
#define HW   (512 * 512)
#define Q    (HW / 4)            // float4 groups per channel plane (65536)
#define TPB  1024
#define NBLOCKS 148              // 1 CTA per SM, all resident: zero tail
#define NWT  16384               // total warp-tiles (32 groups = 512 B each)
#define WT_BASE (NWT / NBLOCKS)  // 110
#define WT_REM  (NWT % NBLOCKS)  // blocks < WT_REM get one extra warp-tile

// Scratch: per-sample confusion matrices conf[b][true][pred].
__device__ int g_conf[NB * NC2];
__device__ unsigned int g_done;   // zero-init; reset by last block each run

__device__ __forceinline__ float4 ldcs256(const float4* p) {
    float4 v;
    asm volatile("ld.global.cs.L2::256B.v4.f32 {%0,%1,%2,%3}, [%4];"
                 : "=f"(v.x), "=f"(v.y), "=f"(v.z), "=f"(v.w)
                 : "l"(p));
    return v;
}

// Fire-and-forget bulk prefetch into L2 (no completion tracking).
__device__ __forceinline__ void prefetch_l2(const void* p, unsigned bytes) {
    asm volatile("cp.async.bulk.prefetch.L2.global [%0], %1;"
                 :: "l"(p), "r"(bytes) : "memory");
}

__global__ void __launch_bounds__(TPB, 1)
conf_kernel(const float* __restrict__ pred,
            const float* __restrict__ tgt,
            float* __restrict__ out) {
    __shared__ int sconf[2][NC2];   // two banks: chunk may straddle 1 sample boundary
    for (int i = threadIdx.x; i < 2 * NC2; i += TPB) (&sconf[0][0])[i] = 0;
    __syncthreads();

    const int j = blockIdx.x;
    const int wt = WT_BASE + (j < WT_REM ? 1 : 0);
    const int start = 32 * (j * WT_BASE + (j < WT_REM ? j : WT_REM));
    const int end = start + wt * 32;    // contiguous group range [start, end)

    for (int base = start; base < end; base += TPB) {
        // Prefetch NEXT iteration's spans into L2: threads 0..41 each issue one
        // bulk prefetch (channel = t>>1, tensor = t&1). Clamped to one sample;
        // straddle tails simply aren't prefetched (hint only).
        const int nb = base + TPB;
        if (threadIdx.x < 2 * NC && nb < end) {
            const int c = threadIdx.x >> 1;
            const int b2 = nb >> 16;
            const int p2 = nb & (Q - 1);
            int cnt = end - nb;
            if (cnt > TPB) cnt = TPB;
            int lim = ((b2 + 1) << 16) - nb;   // stay within sample b2
            if (cnt > lim) cnt = lim;
            const float* basep = (threadIdx.x & 1) ? tgt : pred;
            const float4* addr = reinterpret_cast<const float4*>(basep)
                                 + ((size_t)b2 * NC + c) * Q + p2;
            prefetch_l2(addr, (unsigned)cnt * 16u);
        }

        int g = base + threadIdx.x;
        if (g < end) {
            int b = g >> 16;            // Q = 65536
            int p = g & (Q - 1);

            const float4* pp = reinterpret_cast<const float4*>(pred) + (size_t)b * NC * Q + p;
            const float4* tp = reinterpret_cast<const float4*>(tgt)  + (size_t)b * NC * Q + p;

            float4 pm = ldcs256(pp);
            float4 tm = ldcs256(tp);
            int pax = 0, pay = 0, paz = 0, paw = 0;
            int tax = 0, tay = 0, taz = 0, taw = 0;

            #pragma unroll
            for (int c = 1; c < NC; c++) {
                float4 v = ldcs256(pp + (size_t)c * Q);
                float4 w = ldcs256(tp + (size_t)c * Q);
                if (v.x > pm.x) { pm.x = v.x; pax = c; }
                if (v.y > pm.y) { pm.y = v.y; pay = c; }
                if (v.z > pm.z) { pm.z = v.z; paz = c; }
                if (v.w > pm.w) { pm.w = v.w; paw = c; }
                if (w.x > tm.x) { tm.x = w.x; tax = c; }
                if (w.y > tm.y) { tm.y = w.y; tay = c; }
                if (w.z > tm.z) { tm.z = w.z; taz = c; }
                if (w.w > tm.w) { tm.w = w.w; taw = c; }
            }

            int* sc = sconf[b & 1];
            atomicAdd(&sc[tax * NC + pax], 1);
            atomicAdd(&sc[tay * NC + pay], 1);
            atomicAdd(&sc[taz * NC + paz], 1);
            atomicAdd(&sc[taw * NC + paw], 1);
        }
    }

    __syncthreads();

    // Flush: map banks back to the (at most two) samples this block touched.
    const int b_lo = start >> 16;
    const int b_hi = (end - 1) >> 16;
    for (int i = threadIdx.x; i < NC2; i += TPB) {
        int v = sconf[b_lo & 1][i];
        if (v) atomicAdd(&g_conf[b_lo * NC2 + i], v);
        if (b_hi != b_lo) {
            int v2 = sconf[b_hi & 1][i];
            if (v2) atomicAdd(&g_conf[b_hi * NC2 + i], v2);
        }
    }

    // ---- last-block finalize ----
    __threadfence();
    __shared__ unsigned int s_rank;
    if (threadIdx.x == 0) s_rank = atomicAdd(&g_done, 1u);
    __syncthreads();
    if (s_rank != NBLOCKS - 1) return;

    __shared__ float iou_sum[NB];
    __shared__ int   valid_cnt[NB];
    int t = threadIdx.x;
    if (t < NB) { iou_sum[t] = 0.0f; valid_cnt[t] = 0; }
    if (t == 0) g_done = 0;                 // reset for next invocation
    __syncthreads();

    if (t < NB * NC) {
        int bb = t / NC;
        int c  = t - bb * NC;
        const int* cb = &g_conf[bb * NC2];
        int tpv = __ldcg(&cb[c * NC + c]);
        int row = 0, col = 0;
        #pragma unroll
        for (int k = 0; k < NC; k++) {
            row += __ldcg(&cb[c * NC + k]);   // TP + FN
            col += __ldcg(&cb[k * NC + c]);   // TP + FP
        }
        if (tpv > 0) {
            float iou = (float)tpv / (float)(row + col - tpv);
            atomicAdd(&iou_sum[bb], iou);
            atomicAdd(&valid_cnt[bb], 1);
        }
    }
    __syncthreads();

    // Re-zero scratch for the next invocation (all reads done above).
    for (int i = t; i < NB * NC2; i += TPB) g_conf[i] = 0;

    if (t == 0) {
        float s = 0.0f;
        #pragma unroll
        for (int bb = 0; bb < NB; bb++)
            s += iou_sum[bb] / fmaxf((float)valid_cnt[bb], 1.0f);
        out[0] = s / (float)NB;
    }
}

extern "C" void kernel_launch(void* const* d_in, const int* in_sizes, int n_in,
                              void* d_out, int out_size) {
    const float* pred = (const float*)d_in[0];
    const float* tgt  = (const float*)d_in[1];
    float* out = (float*)d_out;

    conf_kernel<<<NBLOCKS, TPB>>>(pred, tgt, out);
}

// round 17
// speedup vs baseline: 1.2737x; 1.1681x over previous
#include <cuda_runtime.h>

#define NC   21
#define NC2  (NC * NC)
#define NB   8
#define HW   (512 * 512)
#define Q    (HW / 4)            // float4 groups per channel plane (65536)
#define TPB  1024
#define NBLOCKS 148              // 1 CTA per SM, all resident: zero tail
#define NWT  16384               // total warp-tiles (32 groups = 512 B each)
#define WT_BASE (NWT / NBLOCKS)  // 110
#define WT_REM  (NWT % NBLOCKS)  // blocks < WT_REM get one extra warp-tile
#define CHB  1048576             // bytes per channel plane slice (Q * 16)

// Scratch: per-sample confusion matrices conf[b][true][pred].
__device__ int g_conf[NB * NC2];
__device__ unsigned int g_done;   // zero-init; reset by last block each run

// Streaming load with compile-time byte offset: lets ptxas fold the offset
// into the LDG immediate field (|imm| < 8MB) instead of IMAD.WIDE per load.
template <int OFF>
__device__ __forceinline__ float4 ldcs_off(const float4* p) {
    float4 v;
    asm volatile("ld.global.cs.L2::256B.v4.f32 {%0,%1,%2,%3}, [%4+%5];"
                 : "=f"(v.x), "=f"(v.y), "=f"(v.z), "=f"(v.w)
                 : "l"(p), "n"(OFF));
    return v;
}

__global__ void __launch_bounds__(TPB, 1)
conf_kernel(const float* __restrict__ pred,
            const float* __restrict__ tgt,
            float* __restrict__ out) {
    __shared__ int sconf[2][NC2];   // two banks: chunk may straddle 1 sample boundary
    for (int i = threadIdx.x; i < 2 * NC2; i += TPB) (&sconf[0][0])[i] = 0;
    __syncthreads();

    const int j = blockIdx.x;
    const int wt = WT_BASE + (j < WT_REM ? 1 : 0);
    const int start = 32 * (j * WT_BASE + (j < WT_REM ? j : WT_REM));
    const int end = start + wt * 32;    // contiguous group range [start, end)

    for (int base = start; base < end; base += TPB) {
        int g = base + threadIdx.x;
        if (g < end) {
            int b = g >> 16;            // Q = 65536
            int p = g & (Q - 1);

            const float4* pp = reinterpret_cast<const float4*>(pred) + (size_t)b * NC * Q + p;
            const float4* tp = reinterpret_cast<const float4*>(tgt)  + (size_t)b * NC * Q + p;
            const float4* pp8  = pp + (size_t)8 * Q;
            const float4* tp8  = tp + (size_t)8 * Q;
            const float4* pp16 = pp + (size_t)16 * Q;
            const float4* tp16 = tp + (size_t)16 * Q;

            float4 pm = ldcs_off<0>(pp);
            float4 tm = ldcs_off<0>(tp);
            int pax = 0, pay = 0, paz = 0, paw = 0;
            int tax = 0, tay = 0, taz = 0, taw = 0;

            #define STEP(PB, TB, K, C)                                        \
                do {                                                          \
                    float4 v = ldcs_off<(K) * CHB>(PB);                       \
                    float4 w = ldcs_off<(K) * CHB>(TB);                       \
                    if (v.x > pm.x) { pm.x = v.x; pax = (C); }                \
                    if (v.y > pm.y) { pm.y = v.y; pay = (C); }                \
                    if (v.z > pm.z) { pm.z = v.z; paz = (C); }                \
                    if (v.w > pm.w) { pm.w = v.w; paw = (C); }                \
                    if (w.x > tm.x) { tm.x = w.x; tax = (C); }                \
                    if (w.y > tm.y) { tm.y = w.y; tay = (C); }                \
                    if (w.z > tm.z) { tm.z = w.z; taz = (C); }                \
                    if (w.w > tm.w) { tm.w = w.w; taw = (C); }                \
                } while (0)

            STEP(pp,   tp,   1, 1);  STEP(pp,   tp,   2, 2);
            STEP(pp,   tp,   3, 3);  STEP(pp,   tp,   4, 4);
            STEP(pp,   tp,   5, 5);  STEP(pp,   tp,   6, 6);
            STEP(pp,   tp,   7, 7);
            STEP(pp8,  tp8,  0, 8);  STEP(pp8,  tp8,  1, 9);
            STEP(pp8,  tp8,  2, 10); STEP(pp8,  tp8,  3, 11);
            STEP(pp8,  tp8,  4, 12); STEP(pp8,  tp8,  5, 13);
            STEP(pp8,  tp8,  6, 14); STEP(pp8,  tp8,  7, 15);
            STEP(pp16, tp16, 0, 16); STEP(pp16, tp16, 1, 17);
            STEP(pp16, tp16, 2, 18); STEP(pp16, tp16, 3, 19);
            STEP(pp16, tp16, 4, 20);
            #undef STEP

            int* sc = sconf[b & 1];
            atomicAdd(&sc[tax * NC + pax], 1);
            atomicAdd(&sc[tay * NC + pay], 1);
            atomicAdd(&sc[taz * NC + paz], 1);
            atomicAdd(&sc[taw * NC + paw], 1);
        }
    }

    __syncthreads();

    // Flush: map banks back to the (at most two) samples this block touched.
    const int b_lo = start >> 16;
    const int b_hi = (end - 1) >> 16;
    for (int i = threadIdx.x; i < NC2; i += TPB) {
        int v = sconf[b_lo & 1][i];
        if (v) atomicAdd(&g_conf[b_lo * NC2 + i], v);
        if (b_hi != b_lo) {
            int v2 = sconf[b_hi & 1][i];
            if (v2) atomicAdd(&g_conf[b_hi * NC2 + i], v2);
        }
    }

    // ---- last-block finalize ----
    __threadfence();
    __shared__ unsigned int s_rank;
    if (threadIdx.x == 0) s_rank = atomicAdd(&g_done, 1u);
    __syncthreads();
    if (s_rank != NBLOCKS - 1) return;

    __shared__ float iou_sum[NB];
    __shared__ int   valid_cnt[NB];
    int t = threadIdx.x;
    if (t < NB) { iou_sum[t] = 0.0f; valid_cnt[t] = 0; }
    if (t == 0) g_done = 0;                 // reset for next invocation
    __syncthreads();

    if (t < NB * NC) {
        int bb = t / NC;
        int c  = t - bb * NC;
        const int* cb = &g_conf[bb * NC2];
        int tpv = __ldcg(&cb[c * NC + c]);
        int row = 0, col = 0;
        #pragma unroll
        for (int k = 0; k < NC; k++) {
            row += __ldcg(&cb[c * NC + k]);   // TP + FN
            col += __ldcg(&cb[k * NC + c]);   // TP + FP
        }
        if (tpv > 0) {
            float iou = (float)tpv / (float)(row + col - tpv);
            atomicAdd(&iou_sum[bb], iou);
            atomicAdd(&valid_cnt[bb], 1);
        }
    }
    __syncthreads();

    // Re-zero scratch for the next invocation (all reads done above).
    for (int i = t; i < NB * NC2; i += TPB) g_conf[i] = 0;

    if (t == 0) {
        float s = 0.0f;
        #pragma unroll
        for (int bb = 0; bb < NB; bb++)
            s += iou_sum[bb] / fmaxf((float)valid_cnt[bb], 1.0f);
        out[0] = s / (float)NB;
    }
}

extern "C" void kernel_launch(void* const* d_in, const int* in_sizes, int n_in,
                              void* d_out, int out_size) {
    const float* pred = (const float*)d_in[0];
    const float* tgt  = (const float*)d_in[1];
    float* out = (float*)d_out;

    conf_kernel<<<NBLOCKS, TPB>>>(pred, tgt, out);
}